// round 4
// baseline (speedup 1.0000x reference)
#include <cuda_runtime.h>

#define N_NODES 100000
#define N_EDGES 1000000
#define D 64

// Scratch accumulator (residual-initialized, then scatter-added into).
__device__ float g_agg[N_NODES * D];

// ---------------------------------------------------------------------------
// Kernel 1: agg = features  (fuses the "+ features" residual for free)
// ---------------------------------------------------------------------------
__global__ void init_kernel(const float* __restrict__ feat) {
    int i = blockIdx.x * blockDim.x + threadIdx.x;
    const int total = N_NODES * D / 4;  // float4 count = 1.6M
    if (i < total) {
        reinterpret_cast<float4*>(g_agg)[i] =
            reinterpret_cast<const float4*>(feat)[i];
    }
}

// ---------------------------------------------------------------------------
// Kernel 2: for each edge e: agg[dst[e]] += features[src[e]] * w[e]
// 16 threads per edge, each thread handles one float4 (16 B) of the 256 B row.
// red.global.add.v4.f32 -> pure REDG (no return), 4x fewer L2 atomic ops than
// scalar atomicAdd. edge_index is int32 on the wire (JAX default x64=off
// silently downcasts the requested int64).
// ---------------------------------------------------------------------------
__global__ void scatter_kernel(const float* __restrict__ feat,
                               const int* __restrict__ edge_index,
                               const float* __restrict__ edge_weight) {
    int t = blockIdx.x * blockDim.x + threadIdx.x;
    int edge = t >> 4;
    int lane = t & 15;
    if (edge >= N_EDGES) return;

    int src = edge_index[edge];            // row 0: sources
    int dst = edge_index[N_EDGES + edge];  // row 1: destinations
    float w = edge_weight[edge];

    float4 v = reinterpret_cast<const float4*>(feat + (size_t)src * D)[lane];
    v.x *= w; v.y *= w; v.z *= w; v.w *= w;

    float* p = g_agg + (size_t)dst * D + lane * 4;
    asm volatile("red.global.add.v4.f32 [%0], {%1, %2, %3, %4};"
                 :: "l"(p), "f"(v.x), "f"(v.y), "f"(v.z), "f"(v.w)
                 : "memory");
}

// ---------------------------------------------------------------------------
// Kernel 3: out = agg @ W^T + b
// blockDim (64, 4): thread x = output column, y = row within group of 4.
// Each thread keeps its W row (64 floats) in registers; the activation row is
// staged in smem and read as broadcast LDS.128.
// ---------------------------------------------------------------------------
__global__ void __launch_bounds__(256)
gemm_kernel(const float* __restrict__ W,
            const float* __restrict__ b,
            float* __restrict__ out) {
    __shared__ float arow[4][D];

    const int tx = threadIdx.x;  // output column o (0..63)
    const int ty = threadIdx.y;  // row slot (0..3)

    // Load W row o into registers (16 float4 = 64 floats). 16 KB total, hits
    // L1/L2; once per block.
    float wreg[D];
#pragma unroll
    for (int k4 = 0; k4 < D / 4; k4++) {
        float4 w4 = reinterpret_cast<const float4*>(W)[tx * (D / 4) + k4];
        wreg[k4 * 4 + 0] = w4.x;
        wreg[k4 * 4 + 1] = w4.y;
        wreg[k4 * 4 + 2] = w4.z;
        wreg[k4 * 4 + 3] = w4.w;
    }
    const float bias = b[tx];

    for (int row = blockIdx.x * 4 + ty; row < N_NODES; row += gridDim.x * 4) {
        arow[ty][tx] = g_agg[(size_t)row * D + tx];
        __syncthreads();

        float acc = bias;
#pragma unroll
        for (int k4 = 0; k4 < D / 4; k4++) {
            float4 a = *reinterpret_cast<float4*>(&arow[ty][k4 * 4]);
            acc = fmaf(a.x, wreg[k4 * 4 + 0], acc);
            acc = fmaf(a.y, wreg[k4 * 4 + 1], acc);
            acc = fmaf(a.z, wreg[k4 * 4 + 2], acc);
            acc = fmaf(a.w, wreg[k4 * 4 + 3], acc);
        }
        out[(size_t)row * D + tx] = acc;
        __syncthreads();  // protect arow before next iteration's overwrite
    }
}

// ---------------------------------------------------------------------------
extern "C" void kernel_launch(void* const* d_in, const int* in_sizes, int n_in,
                              void* d_out, int out_size) {
    const float* features = (const float*)d_in[0];
    const int* edge_index = (const int*)d_in[1];
    const float* edge_weight = (const float*)d_in[2];
    const float* W = (const float*)d_in[3];
    const float* b = (const float*)d_in[4];
    float* out = (float*)d_out;

    // 1) residual init: 1.6M float4 / 256 = 6250 blocks (exact)
    init_kernel<<<(N_NODES * D / 4 + 255) / 256, 256>>>(features);

    // 2) edge scatter: 16 threads/edge -> 16M threads
    scatter_kernel<<<(N_EDGES * 16 + 255) / 256, 256>>>(features, edge_index,
                                                        edge_weight);

    // 3) fused linear + bias
    dim3 gblock(64, 4);
    gemm_kernel<<<1480, gblock>>>(W, b, out);
}